// round 14
// baseline (speedup 1.0000x reference)
#include <cuda_runtime.h>
#include <cuda_bf16.h>
#include <math.h>
#include <stdint.h>

#define EPSF 1e-6f
#define Bn 16
#define Tn 2048
#define LDn 256
#define NBn 32
#define BTn (Bn*Tn)
#define NCHUNK 64

typedef unsigned long long ull;

// ---------- warp-mma helpers ----------
static __device__ __forceinline__ uint32_t smem_u32(const void* p) {
    uint32_t a;
    asm("{ .reg .u64 t; cvta.to.shared.u64 t, %1; cvt.u32.u64 %0, t; }" : "=r"(a) : "l"(p));
    return a;
}
__device__ __forceinline__ void ldsm4(uint32_t addr, uint32_t& r0, uint32_t& r1,
                                      uint32_t& r2, uint32_t& r3) {
    asm volatile("ldmatrix.sync.aligned.m8n8.x4.shared.b16 {%0,%1,%2,%3}, [%4];"
                 : "=r"(r0), "=r"(r1), "=r"(r2), "=r"(r3) : "r"(addr));
}
__device__ __forceinline__ void mma_bf16(float* c, const uint32_t* a, uint32_t b0, uint32_t b1) {
    asm volatile(
        "mma.sync.aligned.m16n8k16.row.col.f32.bf16.bf16.f32 "
        "{%0,%1,%2,%3},{%4,%5,%6,%7},{%8,%9},{%0,%1,%2,%3};"
        : "+f"(c[0]), "+f"(c[1]), "+f"(c[2]), "+f"(c[3])
        : "r"(a[0]), "r"(a[1]), "r"(a[2]), "r"(a[3]), "r"(b0), "r"(b1));
}

// -------- scratch (device globals) --------
__device__ float2 g_eAiv[(size_t)BTn*LDn];   // (exp(A t), 1/A) packed
__device__ float g_aggA[Bn*NCHUNK*512];
__device__ float g_aggB[Bn*NCHUNK*512];
__device__ float g_carry[Bn*NCHUNK*512];
__device__ float g_Abasis[NBn*LDn];
__device__ float g_initmv[512];
__device__ float g_yvar[LDn];
// bf16 split weights, layout [kchunk(8)][row(256)][k(32)] per matrix
__device__ __align__(16) __nv_bfloat16 g_WMEh[65536];
__device__ __align__(16) __nv_bfloat16 g_WMEl[65536];
__device__ __align__(16) __nv_bfloat16 g_WCEh[65536];
__device__ __align__(16) __nv_bfloat16 g_WCEl[65536];
__device__ __align__(16) __nv_bfloat16 g_Bwh[65536];
__device__ __align__(16) __nv_bfloat16 g_Bwl[65536];

// ---------------- precompute: vectors + A_basis + B_w split (merged) ----------------
__global__ void k_pre_misc(const float* __restrict__ E_w, const float* __restrict__ D,
                           const float* __restrict__ imp, const float* __restrict__ ilv,
                           const float* __restrict__ ylv, const float* __restrict__ B_w) {
    const int tid = threadIdx.x;
    if (blockIdx.x < 64) {
        const int lane = tid & 31;
        const int w = blockIdx.x*8 + (tid >> 5);
        float s = 0.f;
        if (w < 256) {
#pragma unroll
            for (int j = 0; j < 8; j++) { int k = lane + 32*j; s = fmaf(E_w[k*256 + w], imp[k], s); }
        } else {
            const int i = w - 256;
#pragma unroll
            for (int j = 0; j < 8; j++) {
                int k = lane + 32*j; float e = E_w[k*256 + i];
                s = fmaf(e*e, expf(ilv[k]) + EPSF, s);
            }
        }
#pragma unroll
        for (int off = 16; off > 0; off >>= 1) s += __shfl_xor_sync(0xffffffffu, s, off);
        if (lane == 0) {
            g_initmv[w] = s;
            if (w < 256) g_yvar[w] = expf(ylv[w]) + EPSF;
        }
        const int gid = blockIdx.x*256 + tid;
        if (gid < NBn*LDn) g_Abasis[gid] = -(expf(D[gid]) + EPSF);
    } else {
        const int e = blockIdx.x - 64, d = tid;
        const float v = B_w[e*256 + d];
        __nv_bfloat16 h = __float2bfloat16(v);
        __nv_bfloat16 l = __float2bfloat16(v - __bfloat162float(h));
        const int idx = (d >> 5)*8192 + e*32 + (d & 31);
        g_Bwh[idx] = h;
        g_Bwl[idx] = l;
    }
}

// ---------------- precompute: W_ME/W_CE bf16 splits, [kc][f][kk] ----------------
__global__ void k_pre_gemm(const float* __restrict__ E_w, const float* __restrict__ M_w,
                           const float* __restrict__ C_w) {
    const float* X = (blockIdx.z == 0) ? M_w : C_w;
    __nv_bfloat16* oh = (blockIdx.z == 0) ? g_WMEh : g_WCEh;
    __nv_bfloat16* ol = (blockIdx.z == 0) ? g_WMEl : g_WCEl;
    __shared__ float sE[32][33];
    __shared__ float sX[32][33];
    const int tx = threadIdx.x, ty = threadIdx.y;
    const int d0 = blockIdx.x*32, f0 = blockIdx.y*32;
    float acc = 0.f;
    for (int e0 = 0; e0 < 256; e0 += 32) {
        sE[ty][tx] = E_w[(e0+ty)*256 + d0 + tx];
        sX[ty][tx] = X[(f0+ty)*256 + e0 + tx];
        __syncthreads();
#pragma unroll
        for (int e = 0; e < 32; e++) acc = fmaf(sE[e][ty], sX[tx][e], acc);
        __syncthreads();
    }
    const int f = f0 + tx, d = d0 + ty;
    __nv_bfloat16 h = __float2bfloat16(acc);
    __nv_bfloat16 l = __float2bfloat16(acc - __bfloat162float(h));
    const int idx = (d >> 5)*8192 + f*32 + (d & 31);
    oh[idx] = h;
    ol[idx] = l;
}

// ---------------- shared tile geometry ----------------
#define ASTRIDE 528
#define ATILE   16896
#define BSTRIDE 80
#define BTILE   20480

__device__ __forceinline__ void put_split(char* hB, char* lB, int r, int d, float v) {
    __nv_bfloat16 h = __float2bfloat16(v);
    __nv_bfloat16 l = __float2bfloat16(v - __bfloat162float(h));
    const uint32_t off = (uint32_t)r*ASTRIDE + (uint32_t)d*2;
    *(__nv_bfloat16*)(hB + off) = h;
    *(__nv_bfloat16*)(lB + off) = l;
}

// vectorized: 4 consecutive d's, one 8B store per tile
__device__ __forceinline__ void put_split4(char* hB, char* lB, int r, int d4, float4 v) {
    ull hp = 0, lp = 0;
    const float vv[4] = { v.x, v.y, v.z, v.w };
#pragma unroll
    for (int j = 0; j < 4; j++) {
        __nv_bfloat16 h = __float2bfloat16(vv[j]);
        __nv_bfloat16 l = __float2bfloat16(vv[j] - __bfloat162float(h));
        hp |= (ull)__bfloat16_as_ushort(h) << (16*j);
        lp |= (ull)__bfloat16_as_ushort(l) << (16*j);
    }
    const uint32_t off = (uint32_t)r*ASTRIDE + (uint32_t)d4*2;
    *(ull*)(hB + off) = hp;
    *(ull*)(lB + off) = lp;
}

// store one staged chunk (4 uint4 per thread) into B smem tiles
__device__ __forceinline__ void stage_store(char* smc, int base, int tid, const uint4* pb) {
    const int f0 = tid >> 2, seg0 = tid & 3;
    const int q1 = tid + 512;
    const int f1 = q1 >> 2, seg1 = q1 & 3;
    *(uint4*)(smc + base + f0*BSTRIDE + seg0*16) = pb[0];
    *(uint4*)(smc + base + f1*BSTRIDE + seg1*16) = pb[1];
    *(uint4*)(smc + base + BTILE + f0*BSTRIDE + seg0*16) = pb[2];
    *(uint4*)(smc + base + BTILE + f1*BSTRIDE + seg1*16) = pb[3];
}
__device__ __forceinline__ void stage_load(uint4* pb, const uint4* h, const uint4* l, int tid) {
    pb[0] = h[tid];  pb[1] = h[tid + 512];
    pb[2] = l[tid];  pb[3] = l[tid + 512];
}

// ---------------- k_token ----------------
#define TBBASE   33792
#define TCOEF    74752
#define TTIME    79360
#define SMEM_TOKEN (TTIME + 128)
__global__ void __launch_bounds__(512, 2) k_token(const float* __restrict__ Z,
        const float* __restrict__ obs, const float* __restrict__ cW,
        const float* __restrict__ cb, float* __restrict__ alphas_out) {
    extern __shared__ char smc[];
    const uint32_t sbase = smem_u32(smc);
    float* sCoefT = (float*)(smc + TCOEF);
    float* sT     = (float*)(smc + TTIME);
    const int tid = threadIdx.x;
    const int bc = blockIdx.x;
    const int tok0 = bc * 32;

    // prefetch kc=0 weights
    uint4 pb[4];
    stage_load(pb, (const uint4*)g_Bwh, (const uint4*)g_Bwl, tid);

    // ---- phase 1: Z -> bf16 split tiles (float4 / 8B stores) ----
    {
#pragma unroll
        for (int it = 0; it < 4; it++) {
            const int q = tid + it*512;
            const int r = q >> 6, d4 = (q & 63) * 4;
            const float4 z4 = *(const float4*)(Z + (size_t)(tok0 + r)*256 + d4);
            put_split4(smc, smc + ATILE, r, d4, z4);
        }
        if (tid < 32) sT[tid] = obs[tok0 + tid];
    }

    // ---- phase 2: alphas = Z @ B_w^T via 3-term split mma (reg-prefetched B) ----
    const int lane = tid & 31, wid = tid >> 5;
    const int row0 = (wid & 1) * 16;
    const int col0 = (wid >> 1) * 32;
    float cm[4][4];
#pragma unroll
    for (int nt = 0; nt < 4; nt++)
#pragma unroll
        for (int q = 0; q < 4; q++) cm[nt][q] = 0.f;

    const uint32_t aoff = sbase + (uint32_t)(row0 + (lane & 15))*ASTRIDE + (uint32_t)(lane >> 4)*16;
    const uint32_t boff = sbase + TBBASE + (uint32_t)(col0 + (lane & 15))*BSTRIDE + (uint32_t)(lane >> 4)*16;

    for (int kc = 0; kc < 8; kc++) {
        __syncthreads();
        stage_store(smc, TBBASE, tid, pb);
        if (kc < 7)
            stage_load(pb, (const uint4*)g_Bwh + (kc+1)*1024, (const uint4*)g_Bwl + (kc+1)*1024, tid);
        __syncthreads();
#pragma unroll
        for (int kk = 0; kk < 2; kk++) {
            const uint32_t ak = aoff + (uint32_t)(kc*64 + kk*32);
            uint32_t aZh[4], aZl[4];
            ldsm4(ak,         aZh[0], aZh[1], aZh[2], aZh[3]);
            ldsm4(ak + ATILE, aZl[0], aZl[1], aZl[2], aZl[3]);
            uint32_t b[2][2][4];
            const uint32_t bk = boff + (uint32_t)(kk*32);
#pragma unroll
            for (int m = 0; m < 2; m++)
#pragma unroll
                for (int p = 0; p < 2; p++)
                    ldsm4(bk + m*BTILE + p*16*BSTRIDE,
                          b[m][p][0], b[m][p][1], b[m][p][2], b[m][p][3]);
#pragma unroll
            for (int nt = 0; nt < 4; nt++) {
                const int p = nt >> 1, s2 = nt & 1;
                const uint32_t bh0 = b[0][p][s2], bh1 = b[0][p][s2+2];
                const uint32_t bl0 = b[1][p][s2], bl1 = b[1][p][s2+2];
                mma_bf16(cm[nt], aZh, bh0, bh1);
                mma_bf16(cm[nt], aZh, bl0, bl1);
                mma_bf16(cm[nt], aZl, bh0, bh1);
            }
        }
    }
    __syncthreads();

    // ---- epilogue: alphas -> sAL (B area) + gmem; cW -> sCW (A area, pad 260) ----
    float* sAL = (float*)(smc + TBBASE);
    float* sCW = (float*)smc;
    {
        const int r1 = lane >> 2, c2o = (lane & 3)*2;
#pragma unroll
        for (int nt = 0; nt < 4; nt++) {
            const int col = col0 + nt*8 + c2o;
            const int lr0 = row0 + r1, lr1 = row0 + r1 + 8;
            sAL[lr0*256 + col]     = cm[nt][0];
            sAL[lr0*256 + col + 1] = cm[nt][1];
            sAL[lr1*256 + col]     = cm[nt][2];
            sAL[lr1*256 + col + 1] = cm[nt][3];
            *(float2*)(alphas_out + (size_t)(tok0+lr0)*256 + col) = make_float2(cm[nt][0], cm[nt][1]);
            *(float2*)(alphas_out + (size_t)(tok0+lr1)*256 + col) = make_float2(cm[nt][2], cm[nt][3]);
        }
        for (int idx = tid; idx < 32*256; idx += 512)
            sCW[(idx >> 8)*260 + (idx & 255)] = cW[idx];
    }
    __syncthreads();

    // ---- phase 3: logits + softmax (8 warps x 4 tokens, lane = basis n) ----
    if (wid < 8) {
        const int t0 = wid * 4;
        const float4* crow = (const float4*)(sCW + lane*260);
        const float4* a0 = (const float4*)(sAL + (t0+0)*256);
        const float4* a1 = (const float4*)(sAL + (t0+1)*256);
        const float4* a2 = (const float4*)(sAL + (t0+2)*256);
        const float4* a3 = (const float4*)(sAL + (t0+3)*256);
        const float bias = cb[lane];
        float lg0 = bias, lg1 = bias, lg2 = bias, lg3 = bias;
#pragma unroll 4
        for (int q = 0; q < 64; q++) {
            const float4 c4 = crow[q];
            const float4 v0 = a0[q];
            lg0 = fmaf(v0.x, c4.x, lg0); lg0 = fmaf(v0.y, c4.y, lg0);
            lg0 = fmaf(v0.z, c4.z, lg0); lg0 = fmaf(v0.w, c4.w, lg0);
            const float4 v1 = a1[q];
            lg1 = fmaf(v1.x, c4.x, lg1); lg1 = fmaf(v1.y, c4.y, lg1);
            lg1 = fmaf(v1.z, c4.z, lg1); lg1 = fmaf(v1.w, c4.w, lg1);
            const float4 v2 = a2[q];
            lg2 = fmaf(v2.x, c4.x, lg2); lg2 = fmaf(v2.y, c4.y, lg2);
            lg2 = fmaf(v2.z, c4.z, lg2); lg2 = fmaf(v2.w, c4.w, lg2);
            const float4 v3 = a3[q];
            lg3 = fmaf(v3.x, c4.x, lg3); lg3 = fmaf(v3.y, c4.y, lg3);
            lg3 = fmaf(v3.z, c4.z, lg3); lg3 = fmaf(v3.w, c4.w, lg3);
        }
        float lgs[4] = { lg0, lg1, lg2, lg3 };
#pragma unroll
        for (int j = 0; j < 4; j++) {
            float lg = lgs[j];
            float m = lg;
#pragma unroll
            for (int off = 16; off > 0; off >>= 1)
                m = fmaxf(m, __shfl_xor_sync(0xffffffffu, m, off));
            const float e = __expf(lg - m);
            float s = e;
#pragma unroll
            for (int off = 16; off > 0; off >>= 1)
                s += __shfl_xor_sync(0xffffffffu, s, off);
            sCoefT[lane*36 + t0 + j] = e / s;     // transposed: [n][token]
        }
    }
    __syncthreads();

    // ---- phase 4: A_mat + exp terms + half-chunk aggregates ----
    const int c = tid & 255;
    const int h = tid >> 8;
    const int rbase = h * 16;
    float am[16];
#pragma unroll
    for (int rr = 0; rr < 16; rr++) am[rr] = 0.f;
#pragma unroll 4
    for (int n = 0; n < 32; n++) {
        const float ab = g_Abasis[n*256 + c];
        const float4* cp = (const float4*)(sCoefT + n*36 + rbase);
#pragma unroll
        for (int j4 = 0; j4 < 4; j4++) {
            const float4 cc = cp[j4];
            am[j4*4+0] = fmaf(cc.x, ab, am[j4*4+0]);
            am[j4*4+1] = fmaf(cc.y, ab, am[j4*4+1]);
            am[j4*4+2] = fmaf(cc.z, ab, am[j4*4+2]);
            am[j4*4+3] = fmaf(cc.w, ab, am[j4*4+3]);
        }
    }
    float aAm = 1.f, bBm = 0.f, aAv = 1.f, bBv = 0.f;
    float* sAL2 = (float*)(smc + TBBASE);
#pragma unroll 4
    for (int rr = 0; rr < 16; rr++) {
        const int r = rbase + rr;
        const float a = am[rr];
        const float t = sT[r];
        const float eAm = __expf(a * t);
        const float inv = __fdividef(1.0f, a);
        const float al  = sAL2[r*256 + c];
        const float eBm = (eAm - 1.f) * inv * al;
        const float eAv = eAm * eAm;
        const float eBv = 0.5f*(eAv - 1.f)*inv + EPSF;
        const size_t o = (size_t)(tok0 + r)*256 + c;
        g_eAiv[o] = make_float2(eAm, inv);
        bBm = fmaf(eAm, bBm, eBm); aAm *= eAm;
        bBv = fmaf(eAv, bBv, eBv); aAv *= eAv;
    }
    float* sPar = (float*)smc;
    sPar[(h*4+0)*256 + c] = aAm;
    sPar[(h*4+1)*256 + c] = bBm;
    sPar[(h*4+2)*256 + c] = aAv;
    sPar[(h*4+3)*256 + c] = bBv;
    __syncthreads();
    if (tid < 256) {
        const float A0m = sPar[tid],        B0m = sPar[256 + tid];
        const float A0v = sPar[512 + tid],  B0v = sPar[768 + tid];
        const float A1m = sPar[1024 + tid], B1m = sPar[1280 + tid];
        const float A1v = sPar[1536 + tid], B1v = sPar[1792 + tid];
        g_aggA[bc*512 + tid]       = A1m * A0m;
        g_aggB[bc*512 + tid]       = fmaf(A1m, B0m, B1m);
        g_aggA[bc*512 + 256 + tid] = A1v * A0v;
        g_aggB[bc*512 + 256 + tid] = fmaf(A1v, B0v, B1v);
    }
}

// ---------------- warp-parallel scan (coalesced via smem transpose) ----------------
// Block = 512 threads handles (b, 32 channels). Rows padded to 33 floats.
__global__ void __launch_bounds__(512) k_scan2() {
    __shared__ float sA[64*33];
    __shared__ float sB[64*33];
    __shared__ float sC[64*33];
    const int tid = threadIdx.x;
    const int b  = blockIdx.x >> 4;
    const int c0 = (blockIdx.x & 15) * 32;
    const int base = b*NCHUNK*512 + c0;

    // coalesced load: 64 chunks x 32 channels
#pragma unroll
    for (int it = 0; it < 4; it++) {
        const int j = (tid >> 5) + it*16;
        const int cl = tid & 31;
        sA[j*33 + cl] = g_aggA[base + j*512 + cl];
        sB[j*33 + cl] = g_aggB[base + j*512 + cl];
    }
    __syncthreads();

    // 16 warps x 2 channels each: Kogge-Stone over 64 chunks (2 per lane)
    const int lane = tid & 31, wid = tid >> 5;
#pragma unroll
    for (int cc = 0; cc < 2; cc++) {
        const int cl = wid*2 + cc;
        const int j0 = 2*lane;
        const float A0 = sA[j0*33 + cl],     B0 = sB[j0*33 + cl];
        const float A1 = sA[(j0+1)*33 + cl], B1 = sB[(j0+1)*33 + cl];
        const float init = g_initmv[c0 + cl];
        float Ac = A1 * A0;
        float Bc = fmaf(A1, B0, B1);
#pragma unroll
        for (int off = 1; off < 32; off <<= 1) {
            const float Ap = __shfl_up_sync(0xffffffffu, Ac, off);
            const float Bp = __shfl_up_sync(0xffffffffu, Bc, off);
            if (lane >= off) {
                Bc = fmaf(Ac, Bp, Bc);
                Ac = Ac * Ap;
            }
        }
        float Aex = __shfl_up_sync(0xffffffffu, Ac, 1);
        float Bex = __shfl_up_sync(0xffffffffu, Bc, 1);
        if (lane == 0) { Aex = 1.f; Bex = 0.f; }
        const float s0 = fmaf(Aex, init, Bex);
        sC[j0*33 + cl]     = s0;
        sC[(j0+1)*33 + cl] = fmaf(A0, s0, B0);
    }
    __syncthreads();

    // coalesced store of carries
#pragma unroll
    for (int it = 0; it < 4; it++) {
        const int j = (tid >> 5) + it*16;
        const int cl = tid & 31;
        g_carry[base + j*512 + cl] = sC[j*33 + cl];
    }
}

// ---------------- k_fused: two-pass scan-apply + warp-mma output GEMMs ----------------
#define FBBASE   (4*ATILE)
#define SMEM_OUT (FBBASE + 2*BTILE)

__global__ void __launch_bounds__(512, 2) k_fused(const float* __restrict__ Z,
        const float* __restrict__ alphas,
        float* __restrict__ out_means, float* __restrict__ out_stds) {
    extern __shared__ char smc[];
    const uint32_t sbase = smem_u32(smc);
    const int tid = threadIdx.x;
    const int bc = blockIdx.x;
    const int tok0 = bc * 32;

    // prefetch pass-A kc=0 weights
    uint4 pb[4];
    stage_load(pb, (const uint4*)g_WMEh, (const uint4*)g_WMEl, tid);

    // ---- phase 1a: scan apply -> X (mean) and V (std) split tiles ----
    {
        const int d = tid & 255;
        if (tid < 256) {
            float s = g_carry[bc*512 + d];
#pragma unroll 4
            for (int r = 0; r < 32; r++) {
                const size_t o = (size_t)(tok0 + r)*256 + d;
                const float2 ei = g_eAiv[o];
                const float al = alphas[o];
                s = fmaf(ei.x, s, (ei.x - 1.f)*ei.y*al);
                put_split(smc, smc + ATILE, r, d, s);
            }
        } else {
            float s = g_carry[bc*512 + 256 + d];
            const float yv = g_yvar[d];
#pragma unroll 4
            for (int r = 0; r < 32; r++) {
                const size_t o = (size_t)(tok0 + r)*256 + d;
                const float2 ei = g_eAiv[o];
                const float eAv = ei.x * ei.x;
                s = fmaf(eAv, s, 0.5f*(eAv - 1.f)*ei.y + EPSF);
                put_split(smc + 2*ATILE, smc + 3*ATILE, r, d, sqrtf(s + yv));
            }
        }
    }

    const int lane = tid & 31, wid = tid >> 5;
    const int row0 = (wid & 1) * 16;
    const int col0 = (wid >> 1) * 32;
    float cm[4][4], cs[4][4];
#pragma unroll
    for (int nt = 0; nt < 4; nt++)
#pragma unroll
        for (int q = 0; q < 4; q++) { cm[nt][q] = 0.f; cs[nt][q] = 0.f; }

    const uint32_t aoff = sbase + (uint32_t)(row0 + (lane & 15))*ASTRIDE + (uint32_t)(lane >> 4)*16;
    const uint32_t boff = sbase + FBBASE + (uint32_t)(col0 + (lane & 15))*BSTRIDE + (uint32_t)(lane >> 4)*16;

    // ---- pass A: WME against X (means) and V (stds); prefetch next chunk in regs ----
    for (int kc = 0; kc < 8; kc++) {
        __syncthreads();
        stage_store(smc, FBBASE, tid, pb);
        if (kc < 7)
            stage_load(pb, (const uint4*)g_WMEh + (kc+1)*1024, (const uint4*)g_WMEl + (kc+1)*1024, tid);
        else
            stage_load(pb, (const uint4*)g_WCEh, (const uint4*)g_WCEl, tid);
        __syncthreads();
#pragma unroll
        for (int kk = 0; kk < 2; kk++) {
            const uint32_t ak = aoff + (uint32_t)(kc*64 + kk*32);
            uint32_t aXh[4], aXl[4], aVh[4], aVl[4];
            ldsm4(ak,           aXh[0], aXh[1], aXh[2], aXh[3]);
            ldsm4(ak + ATILE,   aXl[0], aXl[1], aXl[2], aXl[3]);
            ldsm4(ak + 2*ATILE, aVh[0], aVh[1], aVh[2], aVh[3]);
            ldsm4(ak + 3*ATILE, aVl[0], aVl[1], aVl[2], aVl[3]);
            uint32_t b[2][2][4];
            const uint32_t bk = boff + (uint32_t)(kk*32);
#pragma unroll
            for (int m = 0; m < 2; m++)
#pragma unroll
                for (int p = 0; p < 2; p++)
                    ldsm4(bk + m*BTILE + p*16*BSTRIDE,
                          b[m][p][0], b[m][p][1], b[m][p][2], b[m][p][3]);
#pragma unroll
            for (int nt = 0; nt < 4; nt++) {
                const int p = nt >> 1, s2 = nt & 1;
                const uint32_t bh0 = b[0][p][s2], bh1 = b[0][p][s2+2];
                const uint32_t bl0 = b[1][p][s2], bl1 = b[1][p][s2+2];
                mma_bf16(cm[nt], aXh, bh0, bh1);
                mma_bf16(cm[nt], aXh, bl0, bl1);
                mma_bf16(cm[nt], aXl, bh0, bh1);
                mma_bf16(cs[nt], aVh, bh0, bh1);
                mma_bf16(cs[nt], aVh, bl0, bl1);
                mma_bf16(cs[nt], aVl, bh0, bh1);
            }
        }
    }
    __syncthreads();

    // ---- phase 1b: H = Z -> tiles 0,1 (aliasing X), float4 ----
    {
#pragma unroll
        for (int it = 0; it < 4; it++) {
            const int q = tid + it*512;
            const int r = q >> 6, d4 = (q & 63) * 4;
            const float4 z4 = *(const float4*)(Z + (size_t)(tok0 + r)*256 + d4);
            put_split4(smc, smc + ATILE, r, d4, z4);
        }
    }

    // ---- pass B: WCE against H (means accumulate); pb holds WCE kc=0 ----
    for (int kc = 0; kc < 8; kc++) {
        __syncthreads();
        stage_store(smc, FBBASE, tid, pb);
        if (kc < 7)
            stage_load(pb, (const uint4*)g_WCEh + (kc+1)*1024, (const uint4*)g_WCEl + (kc+1)*1024, tid);
        __syncthreads();
#pragma unroll
        for (int kk = 0; kk < 2; kk++) {
            const uint32_t ak = aoff + (uint32_t)(kc*64 + kk*32);
            uint32_t aHh[4], aHl[4];
            ldsm4(ak,         aHh[0], aHh[1], aHh[2], aHh[3]);
            ldsm4(ak + ATILE, aHl[0], aHl[1], aHl[2], aHl[3]);
            uint32_t b[2][2][4];
            const uint32_t bk = boff + (uint32_t)(kk*32);
#pragma unroll
            for (int m = 0; m < 2; m++)
#pragma unroll
                for (int p = 0; p < 2; p++)
                    ldsm4(bk + m*BTILE + p*16*BSTRIDE,
                          b[m][p][0], b[m][p][1], b[m][p][2], b[m][p][3]);
#pragma unroll
            for (int nt = 0; nt < 4; nt++) {
                const int p = nt >> 1, s2 = nt & 1;
                const uint32_t bh0 = b[0][p][s2], bh1 = b[0][p][s2+2];
                const uint32_t bl0 = b[1][p][s2], bl1 = b[1][p][s2+2];
                mma_bf16(cm[nt], aHh, bh0, bh1);
                mma_bf16(cm[nt], aHh, bl0, bl1);
                mma_bf16(cm[nt], aHl, bh0, bh1);
            }
        }
    }

    // ---- epilogue ----
    const int r1 = lane >> 2, c2o = (lane & 3)*2;
    const int grow = tok0 + row0 + r1;
#pragma unroll
    for (int nt = 0; nt < 4; nt++) {
        const int col = col0 + nt*8 + c2o;
        const size_t o0 = (size_t)grow*256 + col;
        const size_t o1 = (size_t)(grow + 8)*256 + col;
        *(float2*)(out_means + o0) = make_float2(cm[nt][0], cm[nt][1]);
        *(float2*)(out_means + o1) = make_float2(cm[nt][2], cm[nt][3]);
        *(float2*)(out_stds  + o0) = make_float2(cs[nt][0], cs[nt][1]);
        *(float2*)(out_stds  + o1) = make_float2(cs[nt][2], cs[nt][3]);
    }
}

// ---------------- launch ----------------
extern "C" void kernel_launch(void* const* d_in, const int* in_sizes, int n_in,
                              void* d_out, int out_size) {
    const float* Z   = (const float*)d_in[0];
    const float* obs = (const float*)d_in[1];
    const float* D   = (const float*)d_in[2];
    const float* cW  = (const float*)d_in[3];
    const float* cb  = (const float*)d_in[4];
    const float* E_w = (const float*)d_in[5];
    const float* B_w = (const float*)d_in[6];
    const float* C_w = (const float*)d_in[7];
    const float* M_w = (const float*)d_in[8];
    const float* imp = (const float*)d_in[9];
    const float* ilv = (const float*)d_in[10];
    const float* ylv = (const float*)d_in[11];

    float* out        = (float*)d_out;
    float* out_means  = out;
    float* out_stds   = out + (size_t)BTn * LDn;
    float* out_alphas = out + 2 * (size_t)BTn * LDn;

    cudaFuncSetAttribute(k_token, cudaFuncAttributeMaxDynamicSharedMemorySize, SMEM_TOKEN);
    cudaFuncSetAttribute(k_fused, cudaFuncAttributeMaxDynamicSharedMemorySize, SMEM_OUT);

    k_pre_misc<<<320, 256>>>(E_w, D, imp, ilv, ylv, B_w);
    k_pre_gemm<<<dim3(8,8,2), dim3(32,32)>>>(E_w, M_w, C_w);
    k_token<<<BTn/32, 512, SMEM_TOKEN>>>(Z, obs, cW, cb, out_alphas);
    k_scan2<<<256, 512>>>();
    k_fused<<<BTn/32, 512, SMEM_OUT>>>(Z, out_alphas, out_means, out_stds);
}